// round 2
// baseline (speedup 1.0000x reference)
#include <cuda_runtime.h>
#include <math.h>

#define S_LEN  2048
#define NHEADS 8
#define NBATCH 4
#define HDIM   64
#define NBH    (NBATCH * NHEADS)

// Scratch: projected Q (pre-scaled by D^-0.5), K, V in [B,H,S,D] layout.
__device__ float g_Q[(size_t)NBH * S_LEN * HDIM];
__device__ float g_K[(size_t)NBH * S_LEN * HDIM];
__device__ float g_V[(size_t)NBH * S_LEN * HDIM];

// ---------------------------------------------------------------------------
// Projection: out[(b,h,s),e] = (sum_d x[(b,s,h),d] * W[e,d] + bias[e]) * scale
// One block = 64 rows. 256 threads, 4x4 register tile each (FMA-bound).
// ---------------------------------------------------------------------------
__global__ __launch_bounds__(256) void proj64_kernel(
    const float* __restrict__ x, const float* __restrict__ W,
    const float* __restrict__ bias, float scale, int which)
{
    float* __restrict__ out = (which == 0) ? g_Q : (which == 1) ? g_K : g_V;

    __shared__ float Ws[64 * 64];   // Ws[d*64 + e] = W[e*64 + d]
    __shared__ float xT[64 * 68];   // xT[d*68 + r]

    const int t = threadIdx.x;
    const int rowbase = blockIdx.x * 64;

    #pragma unroll
    for (int i = 0; i < 16; i++) {
        int idx = t + i * 256;
        int e = idx & 63, d = idx >> 6;
        Ws[d * 64 + e] = W[e * 64 + d];      // W is tiny; L2-cached strided read
    }
    #pragma unroll
    for (int i = 0; i < 16; i++) {
        int idx = t + i * 256;
        int r = idx >> 6, d = idx & 63;
        xT[d * 68 + r] = x[(size_t)(rowbase + r) * 64 + d];
    }
    __syncthreads();

    const int ty = t >> 4, tx = t & 15;

    float acc[4][4];
    #pragma unroll
    for (int i = 0; i < 4; i++)
        #pragma unroll
        for (int j = 0; j < 4; j++) acc[i][j] = 0.f;

    #pragma unroll 8
    for (int d = 0; d < 64; d++) {
        float4 xv = *(const float4*)&xT[d * 68 + ty * 4];   // bcast across tx
        float4 wv = *(const float4*)&Ws[d * 64 + tx * 4];   // bcast across ty
        float xa[4] = {xv.x, xv.y, xv.z, xv.w};
        float wa[4] = {wv.x, wv.y, wv.z, wv.w};
        #pragma unroll
        for (int i = 0; i < 4; i++)
            #pragma unroll
            for (int j = 0; j < 4; j++)
                acc[i][j] += xa[i] * wa[j];
    }

    float4 b4 = *(const float4*)&bias[tx * 4];
    float ba[4] = {b4.x, b4.y, b4.z, b4.w};

    #pragma unroll
    for (int i = 0; i < 4; i++) {
        int r = rowbase + ty * 4 + i;     // r = (b*S + s)*H + h
        int b   = r >> 14;                // / (S*H) = /16384
        int rem = r & 16383;
        int s   = rem >> 3;               // / H
        int h   = rem & 7;
        size_t o = ((size_t)(b * NHEADS + h) * S_LEN + s) * 64 + tx * 4;
        float4 ov;
        ov.x = (acc[i][0] + ba[0]) * scale;
        ov.y = (acc[i][1] + ba[1]) * scale;
        ov.z = (acc[i][2] + ba[2]) * scale;
        ov.w = (acc[i][3] + ba[3]) * scale;
        *(float4*)&out[o] = ov;
    }
}

// ---------------------------------------------------------------------------
// Flash attention, fp32, software-pipelined K/V fill.
// Block = 64 q-rows x one (b,h); loop over K/V in chunks of 32.
// 256 threads: scores tile 64x32 (4x2/thread), O tile 64x64 (4x4/thread).
// Next chunk's K/V are prefetched into registers during compute, then
// published to smem at the top of the next iteration.
// ---------------------------------------------------------------------------
__global__ __launch_bounds__(256) void attn_kernel(float* __restrict__ out)
{
    __shared__ float Qt [64 * 68];   // Qt[d*68 + r]
    __shared__ float Kt [64 * 36];   // Kt[d*36 + kc]
    __shared__ float Vsm[32 * 68];   // Vsm[kc*68 + e]
    __shared__ float Ps [64 * 36];   // Ps[r*36 + kc]

    const int t  = threadIdx.x;
    const int ty = t >> 4, tx = t & 15;
    const int qbase = blockIdx.x * 64;
    const int bh    = blockIdx.y;

    const float* __restrict__ Qb = g_Q + (size_t)bh * S_LEN * 64;
    const float* __restrict__ Kb = g_K + (size_t)bh * S_LEN * 64;
    const float* __restrict__ Vb = g_V + (size_t)bh * S_LEN * 64;

    #pragma unroll
    for (int i = 0; i < 16; i++) {
        int idx = t + i * 256;
        int r = idx >> 6, d = idx & 63;
        Qt[d * 68 + r] = Qb[(size_t)(qbase + r) * 64 + d];
    }

    // Prefetch assignment: thread handles row pr (0..31), d-range [pd, pd+8).
    // K publish (scalar, d-major dst): within a warp pd is constant and pr
    // spans 32 distinct rows -> conflict-free. V publish: float4, <=4-way.
    const int pr = t & 31;
    const int pd = (t >> 5) * 8;

    float4 kp0, kp1, vp0, vp1;
    {
        const float* kp = Kb + (size_t)pr * 64 + pd;
        const float* vp = Vb + (size_t)pr * 64 + pd;
        kp0 = *(const float4*)(kp);  kp1 = *(const float4*)(kp + 4);
        vp0 = *(const float4*)(vp);  vp1 = *(const float4*)(vp + 4);
    }

    float O[4][4];
    float mrow[4], lrow[4];
    #pragma unroll
    for (int i = 0; i < 4; i++) {
        mrow[i] = -INFINITY;
        lrow[i] = 0.f;
        #pragma unroll
        for (int j = 0; j < 4; j++) O[i][j] = 0.f;
    }

    for (int kb = 0; kb < S_LEN; kb += 32) {
        __syncthreads();   // prev chunk's consumers done with Kt/Vsm/Ps

        // ---- publish prefetched chunk to smem ----
        Kt[(pd + 0) * 36 + pr] = kp0.x;
        Kt[(pd + 1) * 36 + pr] = kp0.y;
        Kt[(pd + 2) * 36 + pr] = kp0.z;
        Kt[(pd + 3) * 36 + pr] = kp0.w;
        Kt[(pd + 4) * 36 + pr] = kp1.x;
        Kt[(pd + 5) * 36 + pr] = kp1.y;
        Kt[(pd + 6) * 36 + pr] = kp1.z;
        Kt[(pd + 7) * 36 + pr] = kp1.w;
        *(float4*)&Vsm[pr * 68 + pd]     = vp0;
        *(float4*)&Vsm[pr * 68 + pd + 4] = vp1;
        __syncthreads();

        // ---- prefetch next chunk (latency hidden behind compute) ----
        if (kb + 32 < S_LEN) {
            const float* kp = Kb + (size_t)(kb + 32 + pr) * 64 + pd;
            const float* vp = Vb + (size_t)(kb + 32 + pr) * 64 + pd;
            kp0 = *(const float4*)(kp);  kp1 = *(const float4*)(kp + 4);
            vp0 = *(const float4*)(vp);  vp1 = *(const float4*)(vp + 4);
        }

        // ---- scores: 64x32 tile, sc[i][j] for rows ty*4+i, cols tx*2+j ----
        float sc[4][2];
        #pragma unroll
        for (int i = 0; i < 4; i++) { sc[i][0] = 0.f; sc[i][1] = 0.f; }

        #pragma unroll 8
        for (int d = 0; d < 64; d++) {
            float4 q4 = *(const float4*)&Qt[d * 68 + ty * 4];  // bcast over tx
            float2 k2 = *(const float2*)&Kt[d * 36 + tx * 2];  // bcast over ty
            sc[0][0] += q4.x * k2.x;  sc[0][1] += q4.x * k2.y;
            sc[1][0] += q4.y * k2.x;  sc[1][1] += q4.y * k2.y;
            sc[2][0] += q4.z * k2.x;  sc[2][1] += q4.z * k2.y;
            sc[3][0] += q4.w * k2.x;  sc[3][1] += q4.w * k2.y;
        }

        // ---- online softmax update (reduce over the 16 tx lanes) ----
        #pragma unroll
        for (int i = 0; i < 4; i++) {
            float rm = fmaxf(sc[i][0], sc[i][1]);
            rm = fmaxf(rm, __shfl_xor_sync(0xffffffffu, rm, 1));
            rm = fmaxf(rm, __shfl_xor_sync(0xffffffffu, rm, 2));
            rm = fmaxf(rm, __shfl_xor_sync(0xffffffffu, rm, 4));
            rm = fmaxf(rm, __shfl_xor_sync(0xffffffffu, rm, 8));
            float mn   = fmaxf(mrow[i], rm);
            float corr = __expf(mrow[i] - mn);   // exp(-inf)=0 on first chunk
            mrow[i] = mn;
            float p0 = __expf(sc[i][0] - mn);
            float p1 = __expf(sc[i][1] - mn);
            *(float2*)&Ps[(ty * 4 + i) * 36 + tx * 2] = make_float2(p0, p1);
            float rs = p0 + p1;
            rs += __shfl_xor_sync(0xffffffffu, rs, 1);
            rs += __shfl_xor_sync(0xffffffffu, rs, 2);
            rs += __shfl_xor_sync(0xffffffffu, rs, 4);
            rs += __shfl_xor_sync(0xffffffffu, rs, 8);
            lrow[i] = lrow[i] * corr + rs;
            O[i][0] *= corr; O[i][1] *= corr; O[i][2] *= corr; O[i][3] *= corr;
        }
        __syncthreads();

        // ---- O += P @ V : rows ty*4+i, e-cols tx*4+j ----
        #pragma unroll 4
        for (int kc = 0; kc < 32; kc++) {
            float4 v4 = *(const float4*)&Vsm[kc * 68 + tx * 4];  // bcast over ty
            #pragma unroll
            for (int i = 0; i < 4; i++) {
                float p = Ps[(ty * 4 + i) * 36 + kc];            // bcast over tx
                O[i][0] += p * v4.x;
                O[i][1] += p * v4.y;
                O[i][2] += p * v4.z;
                O[i][3] += p * v4.w;
            }
        }
    }

    // ---- normalize + write [B,S,H,D] ----
    const int b = bh >> 3, h = bh & 7;
    #pragma unroll
    for (int i = 0; i < 4; i++) {
        int srow = qbase + ty * 4 + i;
        float inv = 1.0f / lrow[i];
        size_t o = ((size_t)(b * S_LEN + srow) * NHEADS + h) * 64 + tx * 4;
        float4 ov = make_float4(O[i][0] * inv, O[i][1] * inv,
                                O[i][2] * inv, O[i][3] * inv);
        *(float4*)&out[o] = ov;
    }
}

extern "C" void kernel_launch(void* const* d_in, const int* in_sizes, int n_in,
                              void* d_out, int out_size)
{
    const float* query = (const float*)d_in[0];
    const float* key   = (const float*)d_in[1];
    const float* value = (const float*)d_in[2];
    const float* Wq    = (const float*)d_in[3];
    const float* bq    = (const float*)d_in[4];
    const float* Wk    = (const float*)d_in[5];
    const float* bk    = (const float*)d_in[6];
    const float* Wv    = (const float*)d_in[7];
    const float* bv    = (const float*)d_in[8];
    float* out = (float*)d_out;

    const int row_tiles = (NBATCH * S_LEN * NHEADS) / 64;   // 1024
    const float INV_SCALE = 0.125f;                         // 64^-0.5

    proj64_kernel<<<row_tiles, 256>>>(query, Wq, bq, INV_SCALE, 0);
    proj64_kernel<<<row_tiles, 256>>>(key,   Wk, bk, 1.0f,      1);
    proj64_kernel<<<row_tiles, 256>>>(value, Wv, bv, 1.0f,      2);

    dim3 grid(S_LEN / 64, NBH);   // 32 x 32
    attn_kernel<<<grid, 256>>>(out);
}

// round 3
// speedup vs baseline: 1.2776x; 1.2776x over previous
#include <cuda_runtime.h>
#include <math.h>

#define S_LEN  2048
#define NHEADS 8
#define NBATCH 4
#define HDIM   64
#define NBH    (NBATCH * NHEADS)

// Scratch: projected Q (pre-scaled by D^-0.5), K, V in [B,H,S,D] layout.
__device__ float g_Q[(size_t)NBH * S_LEN * HDIM];
__device__ float g_K[(size_t)NBH * S_LEN * HDIM];
__device__ float g_V[(size_t)NBH * S_LEN * HDIM];

// ---------------------------------------------------------------------------
// Projection: out[(b,h,s),e] = (sum_d x[(b,s,h),d] * W[e,d] + bias[e]) * scale
// Block = 128 rows, 256 threads (16x16), 8x4 register tile -> 1.5 B/FMA.
// Dynamic smem: xT[64][132] + Ws[64][68] = 51200 B.
// ---------------------------------------------------------------------------
__global__ __launch_bounds__(256) void proj128_kernel(
    const float* __restrict__ x, const float* __restrict__ W,
    const float* __restrict__ bias, float scale, int which)
{
    extern __shared__ float sm[];
    float* xT = sm;              // xT[d*132 + r], 64 x 132
    float* Ws = sm + 64 * 132;   // Ws[d*68 + e],  64 x 68

    float* __restrict__ out = (which == 0) ? g_Q : (which == 1) ? g_K : g_V;

    const int t = threadIdx.x;
    const int rowbase = blockIdx.x * 128;

    // W transpose fill (one-time, tiny)
    #pragma unroll
    for (int i = 0; i < 16; i++) {
        int idx = t + i * 256;
        int e = idx & 63, d = idx >> 6;
        Ws[d * 68 + e] = W[e * 64 + d];
    }
    // x transpose fill: thread -> row r = t>>1, half = t&1 (d in [half*32, +32))
    {
        const int r = t >> 1, half = t & 1;
        const float* xr = x + (size_t)(rowbase + r) * 64 + half * 32;
        #pragma unroll
        for (int c = 0; c < 8; c++) {
            float4 v = *(const float4*)(xr + c * 4);
            int d = half * 32 + c * 4;
            xT[(d + 0) * 132 + r] = v.x;
            xT[(d + 1) * 132 + r] = v.y;
            xT[(d + 2) * 132 + r] = v.z;
            xT[(d + 3) * 132 + r] = v.w;
        }
    }
    __syncthreads();

    const int ty = t >> 4, tx = t & 15;

    float acc[8][4];
    #pragma unroll
    for (int i = 0; i < 8; i++)
        #pragma unroll
        for (int j = 0; j < 4; j++) acc[i][j] = 0.f;

    #pragma unroll 4
    for (int d = 0; d < 64; d++) {
        float4 xa = *(const float4*)&xT[d * 132 + ty * 8];
        float4 xb = *(const float4*)&xT[d * 132 + ty * 8 + 4];
        float4 w4 = *(const float4*)&Ws[d * 68 + tx * 4];
        float xr[8] = {xa.x, xa.y, xa.z, xa.w, xb.x, xb.y, xb.z, xb.w};
        float wr[4] = {w4.x, w4.y, w4.z, w4.w};
        #pragma unroll
        for (int i = 0; i < 8; i++)
            #pragma unroll
            for (int j = 0; j < 4; j++)
                acc[i][j] += xr[i] * wr[j];
    }

    float4 b4 = *(const float4*)&bias[tx * 4];
    float ba[4] = {b4.x, b4.y, b4.z, b4.w};

    #pragma unroll
    for (int i = 0; i < 8; i++) {
        int r = rowbase + ty * 8 + i;     // r = (b*S + s)*H + h
        int b   = r >> 14;
        int rem = r & 16383;
        int s   = rem >> 3;
        int h   = rem & 7;
        size_t o = ((size_t)(b * NHEADS + h) * S_LEN + s) * 64 + tx * 4;
        float4 ov;
        ov.x = (acc[i][0] + ba[0]) * scale;
        ov.y = (acc[i][1] + ba[1]) * scale;
        ov.z = (acc[i][2] + ba[2]) * scale;
        ov.w = (acc[i][3] + ba[3]) * scale;
        *(float4*)&out[o] = ov;
    }
}

// ---------------------------------------------------------------------------
// Flash attention, fp32, BM=128 q-rows x BN=64 k-cols per chunk.
// 256 threads (16x16): scores tile 8x4/thread, O tile 8x4/thread.
// Dynamic smem 103424 B: Qt[64][132], Kt[64][68], Vs[64][68], Ps[128][68].
// All hot-loop LDS are float4, broadcast or 2-wavefront contiguous.
// ---------------------------------------------------------------------------
__global__ __launch_bounds__(256, 2) void attn_kernel(float* __restrict__ out)
{
    extern __shared__ float sm[];
    float* Qt = sm;                          // [d][r]  64 x 132
    float* Kt = Qt + 64 * 132;               // [d][kc] 64 x 68
    float* Vs = Kt + 64 * 68;                // [kc][e] 64 x 68
    float* Ps = Vs + 64 * 68;                // [r][kc] 128 x 68

    const int t  = threadIdx.x;
    const int ty = t >> 4, tx = t & 15;
    const int qbase = blockIdx.x * 128;
    const int bh    = blockIdx.y;

    const float* __restrict__ Qb = g_Q + (size_t)bh * S_LEN * 64;
    const float* __restrict__ Kb = g_K + (size_t)bh * S_LEN * 64;
    const float* __restrict__ Vb = g_V + (size_t)bh * S_LEN * 64;

    // Q fill (transposed): thread r = t>>1, half = t&1
    {
        const int r = t >> 1, half = t & 1;
        const float* qr = Qb + (size_t)(qbase + r) * 64 + half * 32;
        #pragma unroll
        for (int c = 0; c < 8; c++) {
            float4 v = *(const float4*)(qr + c * 4);
            int d = half * 32 + c * 4;
            Qt[(d + 0) * 132 + r] = v.x;
            Qt[(d + 1) * 132 + r] = v.y;
            Qt[(d + 2) * 132 + r] = v.z;
            Qt[(d + 3) * 132 + r] = v.w;
        }
    }

    float O[8][4];
    float mrow[8], lrow[8];
    #pragma unroll
    for (int i = 0; i < 8; i++) {
        mrow[i] = -INFINITY;
        lrow[i] = 0.f;
        #pragma unroll
        for (int j = 0; j < 4; j++) O[i][j] = 0.f;
    }

    // K/V fill assignment: kc = t>>2 (0..63), part = t&3 -> d in [part*16,+16)
    const int fkc = t >> 2;
    const int fd0 = (t & 3) * 16;

    for (int kb = 0; kb < S_LEN; kb += 64) {
        __syncthreads();   // previous chunk's consumers done with Kt/Vs/Ps

        // ---- fill K (transposed) and V (row-major) ----
        {
            const float* kr = Kb + (size_t)(kb + fkc) * 64 + fd0;
            const float* vr = Vb + (size_t)(kb + fkc) * 64 + fd0;
            #pragma unroll
            for (int c = 0; c < 4; c++) {
                float4 kv = *(const float4*)(kr + c * 4);
                int d = fd0 + c * 4;
                Kt[(d + 0) * 68 + fkc] = kv.x;
                Kt[(d + 1) * 68 + fkc] = kv.y;
                Kt[(d + 2) * 68 + fkc] = kv.z;
                Kt[(d + 3) * 68 + fkc] = kv.w;
                float4 vv = *(const float4*)(vr + c * 4);
                *(float4*)&Vs[fkc * 68 + d] = vv;
            }
        }
        __syncthreads();

        // ---- scores: 128x64 tile, sc[i][j] rows ty*8+i, cols tx*4+j ----
        float sc[8][4];
        #pragma unroll
        for (int i = 0; i < 8; i++)
            #pragma unroll
            for (int j = 0; j < 4; j++) sc[i][j] = 0.f;

        #pragma unroll 4
        for (int d = 0; d < 64; d++) {
            float4 qa = *(const float4*)&Qt[d * 132 + ty * 8];
            float4 qb = *(const float4*)&Qt[d * 132 + ty * 8 + 4];
            float4 k4 = *(const float4*)&Kt[d * 68 + tx * 4];
            float qr[8] = {qa.x, qa.y, qa.z, qa.w, qb.x, qb.y, qb.z, qb.w};
            float kr[4] = {k4.x, k4.y, k4.z, k4.w};
            #pragma unroll
            for (int i = 0; i < 8; i++)
                #pragma unroll
                for (int j = 0; j < 4; j++)
                    sc[i][j] += qr[i] * kr[j];
        }

        // ---- online softmax (reduce over 16 tx lanes; xor<16 stays in group) --
        #pragma unroll
        for (int i = 0; i < 8; i++) {
            float rm = fmaxf(fmaxf(sc[i][0], sc[i][1]),
                             fmaxf(sc[i][2], sc[i][3]));
            rm = fmaxf(rm, __shfl_xor_sync(0xffffffffu, rm, 1));
            rm = fmaxf(rm, __shfl_xor_sync(0xffffffffu, rm, 2));
            rm = fmaxf(rm, __shfl_xor_sync(0xffffffffu, rm, 4));
            rm = fmaxf(rm, __shfl_xor_sync(0xffffffffu, rm, 8));
            float mn   = fmaxf(mrow[i], rm);
            float corr = __expf(mrow[i] - mn);   // exp(-inf)=0 first chunk
            mrow[i] = mn;
            float p0 = __expf(sc[i][0] - mn);
            float p1 = __expf(sc[i][1] - mn);
            float p2 = __expf(sc[i][2] - mn);
            float p3 = __expf(sc[i][3] - mn);
            *(float4*)&Ps[(ty * 8 + i) * 68 + tx * 4] =
                make_float4(p0, p1, p2, p3);
            float rs = (p0 + p1) + (p2 + p3);
            rs += __shfl_xor_sync(0xffffffffu, rs, 1);
            rs += __shfl_xor_sync(0xffffffffu, rs, 2);
            rs += __shfl_xor_sync(0xffffffffu, rs, 4);
            rs += __shfl_xor_sync(0xffffffffu, rs, 8);
            lrow[i] = lrow[i] * corr + rs;
            O[i][0] *= corr; O[i][1] *= corr; O[i][2] *= corr; O[i][3] *= corr;
        }
        __syncthreads();   // Ps visible to all

        // ---- O += P @ V : kc in blocks of 4 (p loads are float4 over kc) ----
        #pragma unroll 2
        for (int blk = 0; blk < 16; blk++) {
            int kc0 = blk * 4;
            float4 v0 = *(const float4*)&Vs[(kc0 + 0) * 68 + tx * 4];
            float4 v1 = *(const float4*)&Vs[(kc0 + 1) * 68 + tx * 4];
            float4 v2 = *(const float4*)&Vs[(kc0 + 2) * 68 + tx * 4];
            float4 v3 = *(const float4*)&Vs[(kc0 + 3) * 68 + tx * 4];
            #pragma unroll
            for (int i = 0; i < 8; i++) {
                float4 p4 = *(const float4*)&Ps[(ty * 8 + i) * 68 + kc0];
                O[i][0] += p4.x * v0.x + p4.y * v1.x + p4.z * v2.x + p4.w * v3.x;
                O[i][1] += p4.x * v0.y + p4.y * v1.y + p4.z * v2.y + p4.w * v3.y;
                O[i][2] += p4.x * v0.z + p4.y * v1.z + p4.z * v2.z + p4.w * v3.z;
                O[i][3] += p4.x * v0.w + p4.y * v1.w + p4.z * v2.w + p4.w * v3.w;
            }
        }
    }

    // ---- normalize + write [B,S,H,D] ----
    const int b = bh >> 3, h = bh & 7;
    #pragma unroll
    for (int i = 0; i < 8; i++) {
        int srow = qbase + ty * 8 + i;
        float inv = 1.0f / lrow[i];
        size_t o = ((size_t)(b * S_LEN + srow) * NHEADS + h) * 64 + tx * 4;
        *(float4*)&out[o] = make_float4(O[i][0] * inv, O[i][1] * inv,
                                        O[i][2] * inv, O[i][3] * inv);
    }
}

extern "C" void kernel_launch(void* const* d_in, const int* in_sizes, int n_in,
                              void* d_out, int out_size)
{
    const float* query = (const float*)d_in[0];
    const float* key   = (const float*)d_in[1];
    const float* value = (const float*)d_in[2];
    const float* Wq    = (const float*)d_in[3];
    const float* bq    = (const float*)d_in[4];
    const float* Wk    = (const float*)d_in[5];
    const float* bk    = (const float*)d_in[6];
    const float* Wv    = (const float*)d_in[7];
    const float* bv    = (const float*)d_in[8];
    float* out = (float*)d_out;

    const int PROJ_SMEM = (64 * 132 + 64 * 68) * 4;                      // 51200
    const int ATTN_SMEM = (64 * 132 + 64 * 68 + 64 * 68 + 128 * 68) * 4; // 103424

    cudaFuncSetAttribute(proj128_kernel,
                         cudaFuncAttributeMaxDynamicSharedMemorySize, PROJ_SMEM);
    cudaFuncSetAttribute(attn_kernel,
                         cudaFuncAttributeMaxDynamicSharedMemorySize, ATTN_SMEM);

    const int row_tiles = (NBATCH * S_LEN * NHEADS) / 128;   // 512
    const float INV_SCALE = 0.125f;                          // 64^-0.5

    proj128_kernel<<<row_tiles, 256, PROJ_SMEM>>>(query, Wq, bq, INV_SCALE, 0);
    proj128_kernel<<<row_tiles, 256, PROJ_SMEM>>>(key,   Wk, bk, 1.0f,      1);
    proj128_kernel<<<row_tiles, 256, PROJ_SMEM>>>(value, Wv, bv, 1.0f,      2);

    dim3 grid(S_LEN / 128, NBH);   // 16 x 32
    attn_kernel<<<grid, 256, ATTN_SMEM>>>(out);
}